// round 1
// baseline (speedup 1.0000x reference)
#include <cuda_runtime.h>
#include <cuda_bf16.h>

// Problem constants (fixed shapes per reference):
//   inputs [B=2, T=16, V=10000, F=32] float32
//   L_vals [NNZ=160000] float32, L_rows sorted int32, L_cols int32
// out[b,t,i,f] = sum_{e: rows[e]==i} vals[e] * inputs[b,t,cols[e],f]

#define BT   32          // B*T
#define NV   10000       // vertices
#define NF   32          // features (== warp size)
#define NNZ_ 160000

// Scratch: CSR row pointers built from the sorted COO rows each launch.
__device__ int g_row_ptr[NV + 1];

// Kernel A: row_ptr[v] = lower_bound(rows, v). rows is sorted ascending.
__global__ void build_row_ptr_kernel(const int* __restrict__ rows) {
    int v = blockIdx.x * blockDim.x + threadIdx.x;
    if (v > NV) return;
    int lo = 0, hi = NNZ_;
    while (lo < hi) {
        int mid = (lo + hi) >> 1;
        if (__ldg(rows + mid) < v) lo = mid + 1;
        else                       hi = mid;
    }
    g_row_ptr[v] = lo;
}

// Kernel B: one warp per (vertex v, slice bt). lane = feature index.
// Gather x[bt, cols[e], lane] (one coalesced 128B line per edge), fma into acc,
// one coalesced 128B store per warp. No atomics (CSR segments are disjoint).
__global__ void __launch_bounds__(256) spmm_warp_kernel(
    const float* __restrict__ x,      // [BT, V, F] contiguous
    const float* __restrict__ vals,   // [NNZ]
    const int*   __restrict__ cols,   // [NNZ]
    float*       __restrict__ out)    // [BT, V, F]
{
    const int warp = threadIdx.x >> 5;
    const int lane = threadIdx.x & 31;
    const int v    = blockIdx.x * 8 + warp;   // 8 warps per CTA
    if (v >= NV) return;
    const int bt = blockIdx.y;

    const float* __restrict__ xs = x + (size_t)bt * NV * NF;

    const int s = g_row_ptr[v];
    const int e = g_row_ptr[v + 1];

    float acc = 0.0f;
    int i = s;
    // Unroll by 2 to expose memory-level parallelism across gathers.
    for (; i + 1 < e; i += 2) {
        int   c0 = __ldg(cols + i);
        int   c1 = __ldg(cols + i + 1);
        float w0 = __ldg(vals + i);
        float w1 = __ldg(vals + i + 1);
        float g0 = __ldg(xs + (size_t)c0 * NF + lane);
        float g1 = __ldg(xs + (size_t)c1 * NF + lane);
        acc = fmaf(w0, g0, acc);
        acc = fmaf(w1, g1, acc);
    }
    if (i < e) {
        int   c0 = __ldg(cols + i);
        float w0 = __ldg(vals + i);
        acc = fmaf(w0, __ldg(xs + (size_t)c0 * NF + lane), acc);
    }

    out[(size_t)bt * NV * NF + (size_t)v * NF + lane] = acc;
}

extern "C" void kernel_launch(void* const* d_in, const int* in_sizes, int n_in,
                              void* d_out, int out_size) {
    const float* x    = (const float*)d_in[0];   // inputs  [B,T,V,F]
    const float* vals = (const float*)d_in[1];   // L_vals  [NNZ]
    const int*   rows = (const int*)  d_in[2];   // L_rows  [NNZ] (sorted)
    const int*   cols = (const int*)  d_in[3];   // L_cols  [NNZ]
    float*       out  = (float*)d_out;

    (void)in_sizes; (void)n_in; (void)out_size;

    // Build CSR row pointers (cheap: 10k binary searches).
    build_row_ptr_kernel<<<(NV + 1 + 255) / 256, 256>>>(rows);

    // SpMM: grid.x covers vertices (8 warps/CTA), grid.y = bt slice.
    // bt outermost so each scheduling wave's gathers concentrate in one
    // 1.28 MB input slice -> L1/L2 reuse.
    dim3 grid((NV + 7) / 8, BT);
    spmm_warp_kernel<<<grid, 256>>>(x, vals, cols, out);
}

// round 3
// speedup vs baseline: 1.6631x; 1.6631x over previous
#include <cuda_runtime.h>
#include <cuda_bf16.h>

// inputs [B=2,T=16,V=10000,F=32] f32; L_vals[160000] f32; L_rows sorted i32; L_cols i32
// out[bt,i,f] = sum_{e: rows[e]==i} vals[e] * x[bt,cols[e],f]

#define BT    32
#define NV    10000
#define NF    32
#define NNZ_  160000

#define WARPS_CTA 8
#define BT_PER    4             // bt slices covered by one warp (via float4 lanes)
#define BTG       (BT / BT_PER) // 8 bt-groups

__device__ int g_row_ptr[NV + 1];

// row_ptr[v] = lower_bound(rows, v); rows sorted ascending.
__global__ void build_row_ptr_kernel(const int* __restrict__ rows) {
    int v = blockIdx.x * blockDim.x + threadIdx.x;
    if (v > NV) return;
    int lo = 0, hi = NNZ_;
    while (lo < hi) {
        int mid = (lo + hi) >> 1;
        if (__ldg(rows + mid) < v) lo = mid + 1;
        else                       hi = mid;
    }
    g_row_ptr[v] = lo;
}

// One warp per (vertex v, bt-group). Lane layout: lane = slice_in_group*8 + f4,
// so each LDG.128 gathers the 128B feature row of one edge across 4 bt slices.
// cols/vals are loaded coalesced (32 edges per 2 loads) and distributed by shfl.
__global__ void __launch_bounds__(WARPS_CTA * 32) spmm_v4_kernel(
    const float* __restrict__ x,      // [BT, V, F]
    const float* __restrict__ vals,   // [NNZ]
    const int*   __restrict__ cols,   // [NNZ]
    float*       __restrict__ out)    // [BT, V, F]
{
    const int warp = threadIdx.x >> 5;
    const int lane = threadIdx.x & 31;
    const int v    = blockIdx.x * WARPS_CTA + warp;
    if (v >= NV) return;   // uniform per warp: no intra-warp divergence below

    const int btg = blockIdx.y;               // 0..7
    const int bt  = btg * BT_PER + (lane >> 3);
    const int f4  = lane & 7;                 // which float4 of the 32-float row

    const float4* __restrict__ xs =
        (const float4*)(x + (size_t)bt * NV * NF) + f4;

    const int s = g_row_ptr[v];
    const int e = g_row_ptr[v + 1];

    float4 acc = make_float4(0.f, 0.f, 0.f, 0.f);

    for (int base = s; base < e; base += 32) {
        int n = e - base;                     // uniform across warp
        if (n > 32) n = 32;
        // Coalesced batch load of up to 32 edges' metadata.
        int   c = 0;
        float w = 0.f;
        if (lane < n) {
            c = __ldg(cols + base + lane);
            w = __ldg(vals + base + lane);
        }
        #pragma unroll 1
        for (int j = 0; j < n; j += 2) {
            int   c0 = __shfl_sync(0xffffffffu, c, j);
            float w0 = __shfl_sync(0xffffffffu, w, j);
            float4 g0 = __ldg(xs + (size_t)c0 * 8);
            if (j + 1 < n) {
                int   c1 = __shfl_sync(0xffffffffu, c, j + 1);
                float w1 = __shfl_sync(0xffffffffu, w, j + 1);
                float4 g1 = __ldg(xs + (size_t)c1 * 8);
                acc.x = fmaf(w0, g0.x, acc.x);
                acc.y = fmaf(w0, g0.y, acc.y);
                acc.z = fmaf(w0, g0.z, acc.z);
                acc.w = fmaf(w0, g0.w, acc.w);
                acc.x = fmaf(w1, g1.x, acc.x);
                acc.y = fmaf(w1, g1.y, acc.y);
                acc.z = fmaf(w1, g1.z, acc.z);
                acc.w = fmaf(w1, g1.w, acc.w);
            } else {
                acc.x = fmaf(w0, g0.x, acc.x);
                acc.y = fmaf(w0, g0.y, acc.y);
                acc.z = fmaf(w0, g0.z, acc.z);
                acc.w = fmaf(w0, g0.w, acc.w);
            }
        }
    }

    float4* o = (float4*)(out + (size_t)bt * NV * NF + (size_t)v * NF) + f4;
    *o = acc;
}

extern "C" void kernel_launch(void* const* d_in, const int* in_sizes, int n_in,
                              void* d_out, int out_size) {
    const float* x    = (const float*)d_in[0];
    const float* vals = (const float*)d_in[1];
    const int*   rows = (const int*)  d_in[2];
    const int*   cols = (const int*)  d_in[3];
    float*       out  = (float*)d_out;

    (void)in_sizes; (void)n_in; (void)out_size;

    build_row_ptr_kernel<<<(NV + 1 + 255) / 256, 256>>>(rows);

    dim3 grid((NV + WARPS_CTA - 1) / WARPS_CTA, BTG);
    spmm_v4_kernel<<<grid, WARPS_CTA * 32>>>(x, vals, cols, out);
}

// round 4
// speedup vs baseline: 1.8314x; 1.1012x over previous
#include <cuda_runtime.h>
#include <cuda_bf16.h>

// inputs [B=2,T=16,V=10000,F=32] f32; L_vals[160000] f32; L_rows sorted i32; L_cols i32
// out[bt,i,f] = sum_{e: rows[e]==i} vals[e] * x[bt,cols[e],f]

#define BT    32
#define NV    10000
#define NF    32
#define NNZ_  160000

#define WARPS_CTA 8
#define BT_PER    4             // bt slices covered by one warp (via float4 lanes)
#define BTG       (BT / BT_PER) // 8 bt-groups

__device__ int g_row_ptr[NV + 1];

// row_ptr[v] = lower_bound(rows, v); rows sorted ascending.
__global__ void build_row_ptr_kernel(const int* __restrict__ rows) {
    int v = blockIdx.x * blockDim.x + threadIdx.x;
    if (v > NV) return;
    int lo = 0, hi = NNZ_;
    while (lo < hi) {
        int mid = (lo + hi) >> 1;
        if (__ldg(rows + mid) < v) lo = mid + 1;
        else                       hi = mid;
    }
    g_row_ptr[v] = lo;
}

// One warp per (vertex v, bt-group). Lane = slice_in_group*8 + f4chunk, so one
// LDG.128 per edge fetches the 128B feature row across 4 bt slices at once.
// cols/vals loaded coalesced (32 edges / 2 loads), distributed by shfl.
// 4-wide gather unroll + dual accumulators for MLP / FMA ILP.
__global__ void __launch_bounds__(WARPS_CTA * 32) spmm_v4_kernel(
    const float* __restrict__ x,      // [BT, V, F]
    const float* __restrict__ vals,   // [NNZ]
    const int*   __restrict__ cols,   // [NNZ]
    float*       __restrict__ out)    // [BT, V, F]
{
    const int warp = threadIdx.x >> 5;
    const int lane = threadIdx.x & 31;
    const int v    = blockIdx.x * WARPS_CTA + warp;
    if (v >= NV) return;   // uniform per warp

    const int btg = blockIdx.y;               // 0..7
    const int bt  = btg * BT_PER + (lane >> 3);
    const int f4  = lane & 7;                 // float4 chunk within the 32-float row

    const float4* __restrict__ xs =
        (const float4*)(x + (size_t)bt * NV * NF) + f4;

    const int s = g_row_ptr[v];
    const int e = g_row_ptr[v + 1];

    float4 acc0 = make_float4(0.f, 0.f, 0.f, 0.f);
    float4 acc1 = make_float4(0.f, 0.f, 0.f, 0.f);

    for (int base = s; base < e; base += 32) {
        int n = e - base;                     // uniform across warp
        if (n > 32) n = 32;
        // Branch-free coalesced batch load of up to 32 edges' metadata.
        int idx = base + lane;
        if (idx > NNZ_ - 1) idx = NNZ_ - 1;   // clamp (only out-of-batch lanes)
        int   c = __ldg(cols + idx);
        float w = __ldg(vals + idx);

        int j = 0;
        #pragma unroll 1
        for (; j + 3 < n; j += 4) {
            int   c0 = __shfl_sync(0xffffffffu, c, j);
            int   c1 = __shfl_sync(0xffffffffu, c, j + 1);
            int   c2 = __shfl_sync(0xffffffffu, c, j + 2);
            int   c3 = __shfl_sync(0xffffffffu, c, j + 3);
            float w0 = __shfl_sync(0xffffffffu, w, j);
            float w1 = __shfl_sync(0xffffffffu, w, j + 1);
            float w2 = __shfl_sync(0xffffffffu, w, j + 2);
            float w3 = __shfl_sync(0xffffffffu, w, j + 3);
            float4 g0 = __ldg(xs + (size_t)c0 * 8);
            float4 g1 = __ldg(xs + (size_t)c1 * 8);
            float4 g2 = __ldg(xs + (size_t)c2 * 8);
            float4 g3 = __ldg(xs + (size_t)c3 * 8);
            acc0.x = fmaf(w0, g0.x, acc0.x);
            acc0.y = fmaf(w0, g0.y, acc0.y);
            acc0.z = fmaf(w0, g0.z, acc0.z);
            acc0.w = fmaf(w0, g0.w, acc0.w);
            acc1.x = fmaf(w1, g1.x, acc1.x);
            acc1.y = fmaf(w1, g1.y, acc1.y);
            acc1.z = fmaf(w1, g1.z, acc1.z);
            acc1.w = fmaf(w1, g1.w, acc1.w);
            acc0.x = fmaf(w2, g2.x, acc0.x);
            acc0.y = fmaf(w2, g2.y, acc0.y);
            acc0.z = fmaf(w2, g2.z, acc0.z);
            acc0.w = fmaf(w2, g2.w, acc0.w);
            acc1.x = fmaf(w3, g3.x, acc1.x);
            acc1.y = fmaf(w3, g3.y, acc1.y);
            acc1.z = fmaf(w3, g3.z, acc1.z);
            acc1.w = fmaf(w3, g3.w, acc1.w);
        }
        #pragma unroll 1
        for (; j < n; ++j) {                  // <=3 leftover edges
            int   c0 = __shfl_sync(0xffffffffu, c, j);
            float w0 = __shfl_sync(0xffffffffu, w, j);
            float4 g0 = __ldg(xs + (size_t)c0 * 8);
            acc0.x = fmaf(w0, g0.x, acc0.x);
            acc0.y = fmaf(w0, g0.y, acc0.y);
            acc0.z = fmaf(w0, g0.z, acc0.z);
            acc0.w = fmaf(w0, g0.w, acc0.w);
        }
    }

    float4 r;
    r.x = acc0.x + acc1.x;
    r.y = acc0.y + acc1.y;
    r.z = acc0.z + acc1.z;
    r.w = acc0.w + acc1.w;

    float4* o = (float4*)(out + (size_t)bt * NV * NF + (size_t)v * NF) + f4;
    *o = r;
}

extern "C" void kernel_launch(void* const* d_in, const int* in_sizes, int n_in,
                              void* d_out, int out_size) {
    const float* x    = (const float*)d_in[0];
    const float* vals = (const float*)d_in[1];
    const int*   rows = (const int*)  d_in[2];
    const int*   cols = (const int*)  d_in[3];
    float*       out  = (float*)d_out;

    (void)in_sizes; (void)n_in; (void)out_size;

    build_row_ptr_kernel<<<(NV + 1 + 255) / 256, 256>>>(rows);

    dim3 grid((NV + WARPS_CTA - 1) / WARPS_CTA, BTG);
    spmm_v4_kernel<<<grid, WARPS_CTA * 32>>>(x, vals, cols, out);
}